// round 7
// baseline (speedup 1.0000x reference)
#include <cuda_runtime.h>
#include <cuda_bf16.h>

// AdaptiveEMA via block-parallel linear-recurrence scan, fully coalesced layout.
//   e[t] = a*e[t-1] + x[t];  num[t] = e[t] - a^201 * e[t-201]  (branchless via
//   64 zero-padded chunks);  out[t] = num[t] * (1 / geometric weight sum).
// TPB=1024, PER_THREAD=4: a thread's segment == one float4 chunk, so global
// loads/stores are perfectly coalesced and e[t] stays in registers for phase 2.

#define S_LEN  4096
#define TPB    1024
#define CHUNKS 1024           // S_LEN / 4
#define PAD    64             // zero chunks in front: e[t<0] == 0, branchless window
#define KWIN   201
#define NWARPS 32

__global__ __launch_bounds__(TPB, 2) void adaptive_ema_kernel(
    const float* __restrict__ x,
    const float* __restrict__ log_hl,
    float* __restrict__ out,
    int F)
{
    __shared__ float4 es4[PAD + CHUNKS];       // 1088 * 16B = 17408 B
    __shared__ float  aggC[NWARPS], aggV[NWARPS];

    const int c    = blockIdx.x;               // channel = b*F + f
    const int f    = c % F;
    const int tid  = threadIdx.x;
    const int lane = tid & 31;
    const int wid  = tid >> 5;

    // ---- per-channel constants ----
    const float inv_hl  = 1.0f / expf(log_hl[f]);
    const float a       = exp2f(-inv_hl);                          // alpha
    const float inv_1ma = 1.0f / (-expm1f(-0.69314718055994531f * inv_hl));
    const float aK      = exp2f(-(float)KWIN * inv_hl);            // alpha^201
    const float r_const = 1.0f / ((1.0f - aK) * inv_1ma + 1e-8f);
    const float a2 = a * a, a3 = a2 * a, a4 = a2 * a2;

    // ---- fully coalesced load: thread owns chunk tid = floats [4t,4t+4) ----
    const float4* xin = reinterpret_cast<const float4*>(x + (size_t)c * S_LEN);
    float4 xv = xin[tid];

    if (tid < PAD) es4[tid] = make_float4(0.f, 0.f, 0.f, 0.f);

    // ---- local serial scan over 4 elements ----
    float v0 = xv.x;
    float v1 = fmaf(a, v0, xv.y);
    float v2 = fmaf(a, v1, xv.z);
    float v3 = fmaf(a, v2, xv.w);

    // segment affine map: E_out = C*E_in + V, C = a^4
    float C = a4;
    float V = v3;

    // ---- Kogge-Stone warp scan over affine maps ----
    #pragma unroll
    for (int d = 1; d < 32; d <<= 1) {
        float Cp = __shfl_up_sync(0xffffffffu, C, d);
        float Vp = __shfl_up_sync(0xffffffffu, V, d);
        if (lane >= d) { V = fmaf(C, Vp, V); C *= Cp; }
    }
    if (lane == 31) { aggC[wid] = C; aggV[wid] = V; }

    // lane-exclusive map (shift by one; lane 0 = identity)
    float Cx = __shfl_up_sync(0xffffffffu, C, 1);
    float Vx = __shfl_up_sync(0xffffffffu, V, 1);
    if (lane == 0) { Cx = 1.0f; Vx = 0.0f; }

    __syncthreads();

    // ---- warp 0 scans the 32 warp aggregates, writes back EXCLUSIVE V ----
    if (wid == 0) {
        float Cw = aggC[lane], Vw = aggV[lane];
        #pragma unroll
        for (int d = 1; d < 32; d <<= 1) {
            float Cp = __shfl_up_sync(0xffffffffu, Cw, d);
            float Vp = __shfl_up_sync(0xffffffffu, Vw, d);
            if (lane >= d) { Vw = fmaf(Cw, Vp, Vw); Cw *= Cp; }
        }
        float Vex = __shfl_up_sync(0xffffffffu, Vw, 1);
        if (lane == 0) Vex = 0.0f;
        aggV[lane] = Vex;        // state entering warp `lane` (applied to E=0)
    }
    __syncthreads();

    // e just before this thread's chunk:
    const float Ein = fmaf(Cx, aggV[wid], Vx);

    // ---- apply carry; stage e chunk to smem; keep in regs ----
    v0 = fmaf(a,  Ein, v0);
    v1 = fmaf(a2, Ein, v1);
    v2 = fmaf(a3, Ein, v2);
    v3 = fmaf(a4, Ein, v3);
    es4[PAD + tid] = make_float4(v0, v1, v2, v3);
    __syncthreads();

    // ---- phase 2: shifted window reads (t-201 = chunk-51 minus 1 elem) ----
    // fa = es4[tid-51] covers t-204..t-201 ; fb = es4[tid-50] covers t-200..t-197
    float4 fa = es4[PAD + tid - 51];
    float s0 = fa.w;
    float s1 = __shfl_down_sync(0xffffffffu, fa.x, 1);
    float s2 = __shfl_down_sync(0xffffffffu, fa.y, 1);
    float s3 = __shfl_down_sync(0xffffffffu, fa.z, 1);
    if (lane == 31) {                       // cross-warp neighbor: one LDS
        float4 fb = es4[PAD + tid - 50];
        s1 = fb.x; s2 = fb.y; s3 = fb.z;
    }

    float n0 = fmaf(-aK, s0, v0);           // pad zeros make t<201 exact
    float n1 = fmaf(-aK, s1, v1);
    float n2 = fmaf(-aK, s2, v2);
    float n3 = fmaf(-aK, s3, v3);

    const int t0 = tid * 4;
    float4 o4;
    if (t0 >= KWIN - 1) {                   // steady state (tid >= 50)
        o4 = make_float4(n0 * r_const, n1 * r_const, n2 * r_const, n3 * r_const);
    } else {                                // warm-up: tw = (1 - a^(t+1))/(1-a)
        float r0 = __fdividef(1.0f, (1.0f - exp2f(-(float)(t0 + 1) * inv_hl)) * inv_1ma + 1e-8f);
        float r1 = __fdividef(1.0f, (1.0f - exp2f(-(float)(t0 + 2) * inv_hl)) * inv_1ma + 1e-8f);
        float r2 = __fdividef(1.0f, (1.0f - exp2f(-(float)(t0 + 3) * inv_hl)) * inv_1ma + 1e-8f);
        float r3 = __fdividef(1.0f, (1.0f - exp2f(-(float)(t0 + 4) * inv_hl)) * inv_1ma + 1e-8f);
        o4 = make_float4(n0 * r0, n1 * r1, n2 * r2, n3 * r3);
    }

    float4* ob = reinterpret_cast<float4*>(out + (size_t)c * S_LEN);
    ob[tid] = o4;                           // fully coalesced STG.128
}

extern "C" void kernel_launch(void* const* d_in, const int* in_sizes, int n_in,
                              void* d_out, int out_size)
{
    const float* x      = (const float*)d_in[0];
    const float* log_hl = (const float*)d_in[1];
    float*       out    = (float*)d_out;

    const int F        = in_sizes[1];            // 256
    const int channels = in_sizes[0] / S_LEN;    // B*F = 8192

    adaptive_ema_kernel<<<channels, TPB>>>(x, log_hl, out, F);
}